// round 5
// baseline (speedup 1.0000x reference)
#include <cuda_runtime.h>
#include <cstdint>

#define MAX_NODES 100000
#define D 128

// Scratch: per-node projections s = x . w_s, d = x . w_d
__device__ float g_s[MAX_NODES];
__device__ float g_d[MAX_NODES];

// Kernel 1: 4 nodes per warp, all loads issued up-front for MLP=4.
__global__ void node_dots_kernel(const float4* __restrict__ x4,
                                 const float* __restrict__ W,
                                 int n_nodes) {
    __shared__ float4 ws4[32];
    __shared__ float4 wd4[32];
    int tid = threadIdx.x;
    if (tid < 32) ws4[tid] = ((const float4*)W)[tid];
    else if (tid < 64) wd4[tid - 32] = ((const float4*)W)[tid - 32 + 32];
    __syncthreads();

    int lane = tid & 31;
    int gwarp = (blockIdx.x * blockDim.x + tid) >> 5;
    int base = gwarp * 4;
    if (base >= n_nodes) return;

    float4 a = ws4[lane];
    float4 c = wd4[lane];

    int n1 = base + 1, n2 = base + 2, n3 = base + 3;
    bool h1 = n1 < n_nodes, h2 = n2 < n_nodes, h3 = n3 < n_nodes;
    float4 v0 = x4[(size_t)base * 32 + lane];
    float4 v1 = h1 ? x4[(size_t)n1 * 32 + lane] : make_float4(0.f, 0.f, 0.f, 0.f);
    float4 v2 = h2 ? x4[(size_t)n2 * 32 + lane] : make_float4(0.f, 0.f, 0.f, 0.f);
    float4 v3 = h3 ? x4[(size_t)n3 * 32 + lane] : make_float4(0.f, 0.f, 0.f, 0.f);

    float s0 = v0.x * a.x + v0.y * a.y + v0.z * a.z + v0.w * a.w;
    float d0 = v0.x * c.x + v0.y * c.y + v0.z * c.z + v0.w * c.w;
    float s1 = v1.x * a.x + v1.y * a.y + v1.z * a.z + v1.w * a.w;
    float d1 = v1.x * c.x + v1.y * c.y + v1.z * c.z + v1.w * c.w;
    float s2 = v2.x * a.x + v2.y * a.y + v2.z * a.z + v2.w * a.w;
    float d2 = v2.x * c.x + v2.y * c.y + v2.z * c.z + v2.w * c.w;
    float s3 = v3.x * a.x + v3.y * a.y + v3.z * a.z + v3.w * a.w;
    float d3 = v3.x * c.x + v3.y * c.y + v3.z * c.z + v3.w * c.w;

    #pragma unroll
    for (int off = 16; off > 0; off >>= 1) {
        s0 += __shfl_down_sync(0xFFFFFFFFu, s0, off);
        d0 += __shfl_down_sync(0xFFFFFFFFu, d0, off);
        s1 += __shfl_down_sync(0xFFFFFFFFu, s1, off);
        d1 += __shfl_down_sync(0xFFFFFFFFu, d1, off);
        s2 += __shfl_down_sync(0xFFFFFFFFu, s2, off);
        d2 += __shfl_down_sync(0xFFFFFFFFu, d2, off);
        s3 += __shfl_down_sync(0xFFFFFFFFu, s3, off);
        d3 += __shfl_down_sync(0xFFFFFFFFu, d3, off);
    }
    if (lane == 0) {
        g_s[base] = s0;
        g_d[base] = d0;
        if (h1) { g_s[n1] = s1; g_d[n1] = d1; }
        if (h2) { g_s[n2] = s2; g_d[n2] = d2; }
        if (h3) { g_s[n3] = s3; g_d[n3] = d3; }
    }
}

__device__ __forceinline__ int4 ldcs_int4(const int4* p) {
    return __ldcs(p);
}

__device__ __forceinline__ float sigmoidf_fast(float z) {
    return 1.0f / (1.0f + __expf(-z));
}

// Kernel 2: 8 edges per thread via split-range layout (thread t handles
// quad t and quad t + n_half, both stride-1 coalesced). 16 independent 4B
// gathers in flight. Index loads use evict-first (__ldcs), output uses
// streaming stores (__stcs) so L1 stays dedicated to the gather tables.
__global__ void edge_score8_kernel(const int4* __restrict__ src4,
                                   const int4* __restrict__ dst4,
                                   const float* __restrict__ b,
                                   float4* __restrict__ out4,
                                   int n_half) {
    int t = blockIdx.x * blockDim.x + threadIdx.x;
    if (t >= n_half) return;
    int q0 = t;
    int q1 = t + n_half;

    int4 sA = __ldcs(src4 + q0);
    int4 sB = __ldcs(src4 + q1);
    int4 dA = __ldcs(dst4 + q0);
    int4 dB = __ldcs(dst4 + q1);
    float bias = __ldg(b);

    // 16 independent gathers
    float sa0 = g_s[sA.x], sa1 = g_s[sA.y], sa2 = g_s[sA.z], sa3 = g_s[sA.w];
    float sb0 = g_s[sB.x], sb1 = g_s[sB.y], sb2 = g_s[sB.z], sb3 = g_s[sB.w];
    float da0 = g_d[dA.x], da1 = g_d[dA.y], da2 = g_d[dA.z], da3 = g_d[dA.w];
    float db0 = g_d[dB.x], db1 = g_d[dB.y], db2 = g_d[dB.z], db3 = g_d[dB.w];

    float4 oA, oB;
    oA.x = sigmoidf_fast(sa0 + da0 + bias);
    oA.y = sigmoidf_fast(sa1 + da1 + bias);
    oA.z = sigmoidf_fast(sa2 + da2 + bias);
    oA.w = sigmoidf_fast(sa3 + da3 + bias);
    oB.x = sigmoidf_fast(sb0 + db0 + bias);
    oB.y = sigmoidf_fast(sb1 + db1 + bias);
    oB.z = sigmoidf_fast(sb2 + db2 + bias);
    oB.w = sigmoidf_fast(sb3 + db3 + bias);
    __stcs(out4 + q0, oA);
    __stcs(out4 + q1, oB);
}

// Tail kernel for leftover edges (not hit for 1e6 edges, but keep correct)
__global__ void edge_score_tail_kernel(const int* __restrict__ src,
                                       const int* __restrict__ dst,
                                       const float* __restrict__ b,
                                       float* __restrict__ out,
                                       int start, int n_edges) {
    int e = start + blockIdx.x * blockDim.x + threadIdx.x;
    if (e >= n_edges) return;
    float logit = g_s[src[e]] + g_d[dst[e]] + __ldg(b);
    out[e] = 1.0f / (1.0f + __expf(-logit));
}

extern "C" void kernel_launch(void* const* d_in, const int* in_sizes, int n_in,
                              void* d_out, int out_size) {
    const float* x   = (const float*)d_in[0];
    const int*   src = (const int*)d_in[1];
    const int*   dst = (const int*)d_in[2];
    const float* W   = (const float*)d_in[3];
    const float* b   = (const float*)d_in[4];
    float*       out = (float*)d_out;

    int n_nodes = in_sizes[0] / D;
    int n_edges = in_sizes[1];

    // Kernel 1: 4 nodes per warp, 8 warps/block -> 32 nodes/block
    {
        int nodes_per_block = 8 * 4;
        int blocks = (n_nodes + nodes_per_block - 1) / nodes_per_block;
        node_dots_kernel<<<blocks, 256>>>((const float4*)x, W, n_nodes);
    }
    // Kernel 2: 8 edges per thread (two quads, split-range)
    {
        int n_quads = n_edges / 4;      // full int4 quads
        int n_half  = n_quads / 2;      // quad-pairs per thread
        int threads = 128;
        int blocks = (n_half + threads - 1) / threads;
        if (blocks > 0)
            edge_score8_kernel<<<blocks, threads>>>((const int4*)src, (const int4*)dst,
                                                    b, (float4*)out, n_half);
        int covered = n_half * 8;
        int tail = n_edges - covered;
        if (tail > 0)
            edge_score_tail_kernel<<<1, 32>>>(src, dst, b, out, covered, n_edges);
    }
}